// round 1
// baseline (speedup 1.0000x reference)
#include <cuda_runtime.h>

// Problem constants
#define BB 4
#define TT 512
#define EE 1024
#define WW 64
#define HH 16
#define DK 64
#define BT (BB*TT)          // 2048 rows

// ---------------------------------------------------------------------------
// Device scratch (allocation-free rule: __device__ globals)
// ---------------------------------------------------------------------------
__device__ float g_qh[BB*HH*TT*DK];   // head-major qlin: [b][h][t][d], 8 MB
__device__ float g_vh[BB*HH*TT*DK];   // head-major vlin
__device__ float g_attn[BT*EE];       // attention output, e = h*DK + d

// ---------------------------------------------------------------------------
// Kernel A: C = x @ W + b for W in {Wq, Wv}, scattered into head-major layout
// 64x64 tile, 256 threads, 4x4 per thread, KT=16
// grid: (E/64=16, BT/64=32, 2)
// ---------------------------------------------------------------------------
__global__ __launch_bounds__(256) void qv_gemm(
    const float* __restrict__ x,
    const float* __restrict__ Wq, const float* __restrict__ bq,
    const float* __restrict__ Wv, const float* __restrict__ bv)
{
    const float* Wm   = blockIdx.z ? Wv   : Wq;
    const float* bias = blockIdx.z ? bv   : bq;
    float*       outp = blockIdx.z ? g_vh : g_qh;

    __shared__ float As[16][68];   // [k][m], pad 68 keeps float4 alignment
    __shared__ float Bs[16][68];   // [k][n]

    const int tx = threadIdx.x & 15;
    const int ty = threadIdx.x >> 4;
    const int m0 = blockIdx.y * 64;
    const int n0 = blockIdx.x * 64;

    const int a_k = threadIdx.x & 15;   // k within tile
    const int a_m = threadIdx.x >> 4;   // m row base (4 rows, stride 16)
    const int b_n = threadIdx.x & 63;
    const int b_k = threadIdx.x >> 6;   // 4 k slices, stride 4

    float acc[4][4] = {};

    for (int k0 = 0; k0 < EE; k0 += 16) {
        #pragma unroll
        for (int i = 0; i < 4; i++)
            As[a_k][a_m + 16*i] = x[(m0 + a_m + 16*i)*EE + k0 + a_k];
        #pragma unroll
        for (int i = 0; i < 4; i++)
            Bs[b_k + 4*i][b_n] = Wm[(k0 + b_k + 4*i)*EE + n0 + b_n];
        __syncthreads();

        #pragma unroll
        for (int k = 0; k < 16; k++) {
            float4 a4 = *(const float4*)(&As[k][ty*4]);
            float4 b4 = *(const float4*)(&Bs[k][tx*4]);
            float ar[4] = {a4.x, a4.y, a4.z, a4.w};
            float br[4] = {b4.x, b4.y, b4.z, b4.w};
            #pragma unroll
            for (int i = 0; i < 4; i++)
                #pragma unroll
                for (int j = 0; j < 4; j++)
                    acc[i][j] = fmaf(ar[i], br[j], acc[i][j]);
        }
        __syncthreads();
    }

    // Epilogue: bias + scatter into head-major [b][h][t][d], c = d*H + h
    #pragma unroll
    for (int i = 0; i < 4; i++) {
        int m = m0 + ty*4 + i;
        int b = m >> 9;          // / 512
        int t = m & 511;
        #pragma unroll
        for (int j = 0; j < 4; j++) {
            int c = n0 + tx*4 + j;
            int h = c & (HH-1);
            int d = c >> 4;
            outp[((b*HH + h)*TT + t)*DK + d] = acc[i][j] + bias[c];
        }
    }
}

// ---------------------------------------------------------------------------
// Kernel B: windowed attention per (b,h, 32-t tile).
// K rows ARE gathered qlin rows (reference uses Wq for keys!), so the K tile
// also contains the Q rows (row 32+t_l).
// grid: (T/32=16, B*H=64), 256 threads
// ---------------------------------------------------------------------------
__global__ __launch_bounds__(256) void attn_kernel()
{
    __shared__ float Ks[96][65];   // window rows t0-32 .. t0+63, pitch 65
    __shared__ float Ps[32][65];   // probs [t][w]

    const int bh = blockIdx.y;             // b*H + h
    const int t0 = blockIdx.x * 32;
    const float* qb = g_qh + bh*TT*DK;
    const float* vb = g_vh + bh*TT*DK;

    // ---- load K tile (clamped window) ----
    for (int idx = threadIdx.x; idx < 96*16; idx += 256) {
        int r  = idx >> 4;
        int c4 = (idx & 15) << 2;
        int src = t0 - 32 + r;
        src = src < 0 ? 0 : (src > TT-1 ? TT-1 : src);
        float4 v = *(const float4*)(qb + src*DK + c4);
        Ks[r][c4]   = v.x; Ks[r][c4+1] = v.y;
        Ks[r][c4+2] = v.z; Ks[r][c4+3] = v.w;
    }
    __syncthreads();

    const int t_l = threadIdx.x >> 3;      // 0..31
    const int wg  = threadIdx.x & 7;       // 0..7
    const float scale = 1.0f / 32.0f;      // 1/sqrt(E)

    // ---- scores: thread owns w = wg + 8*j (conflict-free K reads) ----
    float acc[8] = {};
    const int qrow = 32 + t_l;
    for (int dc = 0; dc < 64; dc += 8) {
        float qv[8];
        #pragma unroll
        for (int dd = 0; dd < 8; dd++) qv[dd] = Ks[qrow][dc+dd];
        #pragma unroll
        for (int j = 0; j < 8; j++) {
            int r = t_l + wg + 8*j;
            #pragma unroll
            for (int dd = 0; dd < 8; dd++)
                acc[j] = fmaf(qv[dd], Ks[r][dc+dd], acc[j]);
        }
    }

    // ---- softmax over the 8-lane group (same t, wg = 0..7) ----
    float m = -1e30f;
    #pragma unroll
    for (int j = 0; j < 8; j++) { acc[j] *= scale; m = fmaxf(m, acc[j]); }
    #pragma unroll
    for (int off = 1; off < 8; off <<= 1)
        m = fmaxf(m, __shfl_xor_sync(0xffffffffu, m, off));
    float s = 0.f, p[8];
    #pragma unroll
    for (int j = 0; j < 8; j++) { p[j] = __expf(acc[j] - m); s += p[j]; }
    #pragma unroll
    for (int off = 1; off < 8; off <<= 1)
        s += __shfl_xor_sync(0xffffffffu, s, off);
    float inv = 1.0f / s;
    #pragma unroll
    for (int j = 0; j < 8; j++)
        Ps[t_l][wg + 8*j] = p[j] * inv;

    __syncthreads();   // all score reads done; safe to overwrite Ks with V

    // ---- load V tile into same buffer ----
    for (int idx = threadIdx.x; idx < 96*16; idx += 256) {
        int r  = idx >> 4;
        int c4 = (idx & 15) << 2;
        int src = t0 - 32 + r;
        src = src < 0 ? 0 : (src > TT-1 ? TT-1 : src);
        float4 v = *(const float4*)(vb + src*DK + c4);
        Ks[r][c4]   = v.x; Ks[r][c4+1] = v.y;
        Ks[r][c4+2] = v.z; Ks[r][c4+3] = v.w;
    }
    __syncthreads();

    // ---- output: thread owns (t_l, d = dg*8 + i) ----
    const int dg = wg;
    float ao[8] = {};
    #pragma unroll 8
    for (int w = 0; w < 64; w++) {
        float pw = Ps[t_l][w];
        int r = t_l + w;
        #pragma unroll
        for (int i = 0; i < 8; i++)
            ao[i] = fmaf(pw, Ks[r][dg*8 + i], ao[i]);
    }

    // write g_attn[(b*T + t)*E + h*DK + d]  (H-major merge)
    const int b = bh >> 4, h = bh & 15;
    const int t = t0 + t_l;
    float* op = g_attn + (b*TT + t)*EE + h*DK + dg*8;
    #pragma unroll
    for (int i = 0; i < 8; i++) op[i] = ao[i];
}

// ---------------------------------------------------------------------------
// Kernel C: d_out = g_attn @ Wo + bo   (same SGEMM, direct output)
// grid: (E/64=16, BT/64=32)
// ---------------------------------------------------------------------------
__global__ __launch_bounds__(256) void out_gemm(
    const float* __restrict__ Wo, const float* __restrict__ bo,
    float* __restrict__ out)
{
    __shared__ float As[16][68];
    __shared__ float Bs[16][68];

    const int tx = threadIdx.x & 15;
    const int ty = threadIdx.x >> 4;
    const int m0 = blockIdx.y * 64;
    const int n0 = blockIdx.x * 64;

    const int a_k = threadIdx.x & 15;
    const int a_m = threadIdx.x >> 4;
    const int b_n = threadIdx.x & 63;
    const int b_k = threadIdx.x >> 6;

    float acc[4][4] = {};

    for (int k0 = 0; k0 < EE; k0 += 16) {
        #pragma unroll
        for (int i = 0; i < 4; i++)
            As[a_k][a_m + 16*i] = g_attn[(m0 + a_m + 16*i)*EE + k0 + a_k];
        #pragma unroll
        for (int i = 0; i < 4; i++)
            Bs[b_k + 4*i][b_n] = Wo[(k0 + b_k + 4*i)*EE + n0 + b_n];
        __syncthreads();

        #pragma unroll
        for (int k = 0; k < 16; k++) {
            float4 a4 = *(const float4*)(&As[k][ty*4]);
            float4 b4 = *(const float4*)(&Bs[k][tx*4]);
            float ar[4] = {a4.x, a4.y, a4.z, a4.w};
            float br[4] = {b4.x, b4.y, b4.z, b4.w};
            #pragma unroll
            for (int i = 0; i < 4; i++)
                #pragma unroll
                for (int j = 0; j < 4; j++)
                    acc[i][j] = fmaf(ar[i], br[j], acc[i][j]);
        }
        __syncthreads();
    }

    #pragma unroll
    for (int i = 0; i < 4; i++) {
        int m = m0 + ty*4 + i;
        #pragma unroll
        for (int j = 0; j < 4; j++) {
            int c = n0 + tx*4 + j;
            out[m*EE + c] = acc[i][j] + bo[c];
        }
    }
}

// ---------------------------------------------------------------------------
// Inputs (metadata order): 0:x  1:position_mask(unused)  2:Wq 3:bq 4:Wv 5:bv
//                          6:Wo 7:bo.  Output: float32 [B,T,E].
// ---------------------------------------------------------------------------
extern "C" void kernel_launch(void* const* d_in, const int* in_sizes, int n_in,
                              void* d_out, int out_size)
{
    const float* x  = (const float*)d_in[0];
    const float* Wq = (const float*)d_in[2];
    const float* bq = (const float*)d_in[3];
    const float* Wv = (const float*)d_in[4];
    const float* bv = (const float*)d_in[5];
    const float* Wo = (const float*)d_in[6];
    const float* bo = (const float*)d_in[7];
    float* out = (float*)d_out;

    qv_gemm<<<dim3(EE/64, BT/64, 2), 256>>>(x, Wq, bq, Wv, bv);
    attn_kernel<<<dim3(TT/32, BB*HH), 256>>>();
    out_gemm<<<dim3(EE/64, BT/64), 256>>>(Wo, bo, out);
}